// round 4
// baseline (speedup 1.0000x reference)
#include <cuda_runtime.h>
#include <math.h>
#include <stdint.h>

#define NC 200000
#define NF 64
#define NH 128
#define NS 512

// ---- scratch ----
__device__ float    d_logits[NC];
__device__ float    d_e[NC];
__device__ float    d_w2k[NH];
__device__ uint32_t d_W1tf[NF * NH];  // W1 pre-converted to tf32 bits
__device__ float    d_c2;
__device__ unsigned d_gmax_u;
__device__ int      d_pcount;
__device__ int      d_pidx[NC];
__device__ float    d_pval[NC];
__device__ float    d_sums[NS];
__device__ float    d_sl[NS];
__device__ int      d_cnt[NS];

// float<->uint order-preserving (for atomicMax on floats)
__device__ __forceinline__ unsigned ford(float f) {
    unsigned u = __float_as_uint(f);
    return (u & 0x80000000u) ? ~u : (u | 0x80000000u);
}
__device__ __forceinline__ float funord(unsigned u) {
    return __uint_as_float((u & 0x80000000u) ? (u ^ 0x80000000u) : ~u);
}

__device__ __forceinline__ uint32_t f2tf32(float v) {
    uint32_t u;
    asm("cvt.rna.tf32.f32 %0, %1;" : "=r"(u) : "f"(v));
    return u;
}

__device__ __forceinline__ void mma_tf32(float c[4], const uint32_t a[4],
                                         uint32_t b0, uint32_t b1) {
    asm volatile(
        "mma.sync.aligned.m16n8k8.row.col.f32.tf32.tf32.f32 "
        "{%0,%1,%2,%3}, {%4,%5,%6,%7}, {%8,%9}, {%0,%1,%2,%3};"
        : "+f"(c[0]), "+f"(c[1]), "+f"(c[2]), "+f"(c[3])
        : "r"(a[0]), "r"(a[1]), "r"(a[2]), "r"(a[3]), "r"(b0), "r"(b1));
}

// ---- launch 0: init state + fold W2/key_w + pre-convert W1 to tf32 ----
__global__ void k_prep(const float* __restrict__ W1, const float* __restrict__ W2,
                       const float* __restrict__ b2, const float* __restrict__ kw) {
    __shared__ float kws[NH];
    __shared__ float red[4];
    int h = threadIdx.x;  // 128
    kws[h] = kw[h];
    // init per-call state
    for (int i = h; i < NS; i += 128) d_sums[i] = 0.f;
    if (h == 0) { d_gmax_u = 0u; d_pcount = 0; }
    __syncthreads();
    float s = 0.f;
#pragma unroll 8
    for (int j = 0; j < NH; j++) s += W2[h * NH + j] * kws[j];
    d_w2k[h] = s;
    float c = b2[h] * kws[h];
    for (int o = 16; o; o >>= 1) c += __shfl_xor_sync(0xffffffffu, c, o);
    if ((h & 31) == 0) red[h >> 5] = c;
    __syncthreads();
    if (h == 0) d_c2 = red[0] + red[1] + red[2] + red[3];
    for (int i = h; i < NF * NH; i += 128) d_W1tf[i] = f2tf32(W1[i]);
}

// ================== launch 1: tf32 mma.sync MLP (+ inline global max) ==================
// Per CTA: 128 clauses x NH=128 hidden, K=NF=64.
// A = features [128 x 64] row-major smem (stride 68 floats), B = W1tf [64 x 128] (stride 136)
#define FS 68
#define WS 136
#define OFF_FEAT 0
#define OFF_W1   (128 * FS * 4)
#define OFF_B1   (OFF_W1 + 64 * WS * 4)
#define OFF_WK   (OFF_B1 + 512)
#define OFF_MAX  (OFF_WK + 512)
#define SMEM_MLP (OFF_MAX + 64)

__global__ void __launch_bounds__(128) k_mlp(const float* __restrict__ feat,
                                             const float* __restrict__ b1) {
    extern __shared__ char smem[];
    float*    featS = (float*)(smem + OFF_FEAT);
    uint32_t* W1S   = (uint32_t*)(smem + OFF_W1);
    float*    b1s   = (float*)(smem + OFF_B1);
    float*    wks   = (float*)(smem + OFF_WK);
    float*    wmax  = (float*)(smem + OFF_MAX);

    int tid = threadIdx.x;
    int wid = tid >> 5, lane = tid & 31;
    int g = lane >> 2, q = lane & 3;
    int base = blockIdx.x * 128;

    // stage A tile (zero-fill OOB rows)
    for (int i = tid; i < 128 * 16; i += 128) {
        int row = i >> 4, f4 = i & 15;
        float4 v = make_float4(0.f, 0.f, 0.f, 0.f);
        int c = base + row;
        if (c < NC) v = *(const float4*)(feat + (size_t)c * NF + f4 * 4);
        *(float4*)(featS + row * FS + f4 * 4) = v;
    }
    // stage pre-converted W1 tile
    for (int i = tid; i < 64 * 32; i += 128) {
        int row = i >> 5, f4 = i & 31;
        uint4 v = *(const uint4*)(d_W1tf + row * NH + f4 * 4);
        *(uint4*)(W1S + row * WS + f4 * 4) = v;
    }
    if (tid < NH) { b1s[tid] = b1[tid]; wks[tid] = d_w2k[tid]; }
    __syncthreads();

    // load A fragments once: a[mt][kt][4]
    uint32_t a[2][8][4];
#pragma unroll
    for (int mt = 0; mt < 2; mt++) {
        int r0 = wid * 32 + mt * 16 + g;
#pragma unroll
        for (int kt = 0; kt < 8; kt++) {
            int k0 = kt * 8;
            a[mt][kt][0] = f2tf32(featS[r0 * FS + k0 + q]);
            a[mt][kt][1] = f2tf32(featS[(r0 + 8) * FS + k0 + q]);
            a[mt][kt][2] = f2tf32(featS[r0 * FS + k0 + q + 4]);
            a[mt][kt][3] = f2tf32(featS[(r0 + 8) * FS + k0 + q + 4]);
        }
    }

    float acc[2][2] = {{0.f, 0.f}, {0.f, 0.f}};
#pragma unroll
    for (int nt = 0; nt < 16; nt++) {
        float c0[4] = {0.f, 0.f, 0.f, 0.f};
        float c1[4] = {0.f, 0.f, 0.f, 0.f};
#pragma unroll
        for (int kt = 0; kt < 8; kt++) {
            int kk = kt * 8;
            uint32_t b0  = W1S[(kk + q) * WS + nt * 8 + g];
            uint32_t b1f = W1S[(kk + q + 4) * WS + nt * 8 + g];
            mma_tf32(c0, a[0][kt], b0, b1f);
            mma_tf32(c1, a[1][kt], b0, b1f);
        }
        int col0 = nt * 8 + 2 * q, col1 = col0 + 1;
        float bb0 = b1s[col0], bb1 = b1s[col1];
        float wk0 = wks[col0], wk1 = wks[col1];
        acc[0][0] += fmaxf(c0[0] + bb0, 0.f) * wk0 + fmaxf(c0[1] + bb1, 0.f) * wk1;
        acc[0][1] += fmaxf(c0[2] + bb0, 0.f) * wk0 + fmaxf(c0[3] + bb1, 0.f) * wk1;
        acc[1][0] += fmaxf(c1[0] + bb0, 0.f) * wk0 + fmaxf(c1[1] + bb1, 0.f) * wk1;
        acc[1][1] += fmaxf(c1[2] + bb0, 0.f) * wk0 + fmaxf(c1[3] + bb1, 0.f) * wk1;
    }

    // quad-reduce columns; store logits; track local max
    float c2v = d_c2;
    float lmax = -3.4e38f;
#pragma unroll
    for (int mt = 0; mt < 2; mt++) {
#pragma unroll
        for (int rh = 0; rh < 2; rh++) {
            float v = acc[mt][rh];
            v += __shfl_xor_sync(0xffffffffu, v, 1);
            v += __shfl_xor_sync(0xffffffffu, v, 2);
            v += c2v;
            int c = base + wid * 32 + mt * 16 + rh * 8 + g;
            if (c < NC) {
                if (q == 0) d_logits[c] = v;
                lmax = fmaxf(lmax, v);
            }
        }
    }
    // warp max -> smem -> one atomic per block
    for (int o = 16; o; o >>= 1) lmax = fmaxf(lmax, __shfl_xor_sync(0xffffffffu, lmax, o));
    if (lane == 0) wmax[wid] = lmax;
    __syncthreads();
    if (tid == 0) {
        float m = fmaxf(fmaxf(wmax[0], wmax[1]), fmaxf(wmax[2], wmax[3]));
        atomicMax(&d_gmax_u, ford(m));
    }
}

// ---- launch 2: e[n] = exp(logit - gmax); compact proof ----
__global__ void k_exp(const int* __restrict__ proof) {
    float gmax = funord(d_gmax_u);
    int t = blockIdx.x * blockDim.x + threadIdx.x;
    for (int n = t; n < NC; n += gridDim.x * blockDim.x) {
        float l = d_logits[n];
        d_e[n] = expf(l - gmax);
        if (proof[n]) {
            int p = atomicAdd(&d_pcount, 1);
            d_pidx[p] = n;
            d_pval[p] = l;
        }
    }
}

// ---- launch 3: denominator; e-chunk in registers, warp-per-step ----
#define CHUNK 2048
#define DTPB 256
__global__ void __launch_bounds__(DTPB) k_denom(const int* __restrict__ sel) {
    int tid = threadIdx.x;
    int w = tid >> 5, l = tid & 31;
    int base = blockIdx.x * CHUNK;
    bool fast = (base + CHUNK) <= NC;

    // lane l holds e[base + j*128 + l*4 .. +3] for j = 0..15
    float4 ej[16];
    if (fast) {
#pragma unroll
        for (int j = 0; j < 16; j++)
            ej[j] = *(const float4*)(d_e + base + j * 128 + l * 4);
    } else {
#pragma unroll
        for (int j = 0; j < 16; j++) {
            int n0 = base + j * 128 + l * 4;
            ej[j].x = (n0 + 0 < NC) ? d_e[n0 + 0] : 0.f;
            ej[j].y = (n0 + 1 < NC) ? d_e[n0 + 1] : 0.f;
            ej[j].z = (n0 + 2 < NC) ? d_e[n0 + 2] : 0.f;
            ej[j].w = (n0 + 3 < NC) ? d_e[n0 + 3] : 0.f;
        }
    }

    for (int si = 0; si < 8; si++) {
        int s = blockIdx.y * 64 + si * 8 + w;
        const int* mrow = sel + (size_t)s * NC + base;
        float acc = 0.f;
        if (fast) {
            const int4* m4 = (const int4*)mrow;
#pragma unroll
            for (int j = 0; j < 16; j++) {
                int4 m = m4[j * 32 + l];
                if (m.x) acc += ej[j].x;
                if (m.y) acc += ej[j].y;
                if (m.z) acc += ej[j].z;
                if (m.w) acc += ej[j].w;
            }
        } else {
#pragma unroll
            for (int j = 0; j < 16; j++) {
                int n0 = base + j * 128 + l * 4;
                if (n0 + 0 < NC && mrow[j * 128 + l * 4 + 0]) acc += ej[j].x;
                if (n0 + 1 < NC && mrow[j * 128 + l * 4 + 1]) acc += ej[j].y;
                if (n0 + 2 < NC && mrow[j * 128 + l * 4 + 2]) acc += ej[j].z;
                if (n0 + 3 < NC && mrow[j * 128 + l * 4 + 3]) acc += ej[j].w;
            }
        }
        for (int o = 16; o; o >>= 1) acc += __shfl_xor_sync(0xffffffffu, acc, o);
        if (l == 0) atomicAdd(&d_sums[s], acc);
    }
}

// ---- launch 4: numerator over compacted proof set ----
__global__ void k_numer(const int* __restrict__ sel) {
    int s = blockIdx.x;
    int tid = threadIdx.x;  // 256
    int P = d_pcount;
    float sl = 0.f;
    int cnt = 0;
    const int* srow = sel + (size_t)s * NC;
    for (int j = tid; j < P; j += 256) {
        int n = d_pidx[j];
        if (srow[n]) { sl += d_pval[j]; cnt++; }
    }
    for (int o = 16; o; o >>= 1) {
        sl += __shfl_xor_sync(0xffffffffu, sl, o);
        cnt += __shfl_xor_sync(0xffffffffu, cnt, o);
    }
    __shared__ float rs[8];
    __shared__ int rc[8];
    if ((tid & 31) == 0) { rs[tid >> 5] = sl; rc[tid >> 5] = cnt; }
    __syncthreads();
    if (tid == 0) {
        float ts = 0.f;
        int tc = 0;
#pragma unroll
        for (int wv = 0; wv < 8; wv++) { ts += rs[wv]; tc += rc[wv]; }
        d_sl[s] = ts;
        d_cnt[s] = tc;
    }
}

// ---- launch 5: final loss ----
__global__ void k_final(float* out) {
    float gmax = funord(d_gmax_u);
    int t = threadIdx.x;  // 512
    float v = (gmax + logf(d_sums[t])) - d_sl[t] / (float)d_cnt[t];
    for (int o = 16; o; o >>= 1) v += __shfl_xor_sync(0xffffffffu, v, o);
    __shared__ float red[16];
    if ((t & 31) == 0) red[t >> 5] = v;
    __syncthreads();
    if (t == 0) {
        float tot = 0.f;
#pragma unroll
        for (int w = 0; w < 16; w++) tot += red[w];
        out[0] = tot / (float)NS;
    }
}

extern "C" void kernel_launch(void* const* d_in, const int* in_sizes, int n_in,
                              void* d_out, int out_size) {
    const float* feat = (const float*)d_in[0];
    const float* W1   = (const float*)d_in[1];
    const float* b1   = (const float*)d_in[2];
    const float* W2   = (const float*)d_in[3];
    const float* b2   = (const float*)d_in[4];
    const float* kw   = (const float*)d_in[5];
    const int*   sel  = (const int*)d_in[6];
    const int*   proof= (const int*)d_in[7];
    float* out = (float*)d_out;

    static int smem_set = 0;
    if (!smem_set) {
        cudaFuncSetAttribute(k_mlp, cudaFuncAttributeMaxDynamicSharedMemorySize, SMEM_MLP);
        smem_set = 1;
    }

    k_prep<<<1, 128>>>(W1, W2, b2, kw);
    k_mlp<<<(NC + 127) / 128, 128, SMEM_MLP>>>(feat, b1);
    k_exp<<<200, 256>>>(proof);
    dim3 dg((NC + CHUNK - 1) / CHUNK, NS / 64);
    k_denom<<<dg, DTPB>>>(sel);
    k_numer<<<NS, 256>>>(sel);
    k_final<<<1, NS>>>(out);
}

// round 5
// speedup vs baseline: 1.3480x; 1.3480x over previous
#include <cuda_runtime.h>
#include <math.h>
#include <stdint.h>

#define NC 200000
#define NF 64
#define NH 128
#define NS 512

// ---- scratch ----
__device__ float    d_logits[NC];
__device__ float    d_w2k[NH];
__device__ uint32_t d_W1tf[NF * NH];  // W1 pre-converted to tf32 bits
__device__ float    d_c2;
__device__ unsigned d_gmax_u;
__device__ float    d_sums[NS];
__device__ float    d_sl[NS];
__device__ float    d_cntf[NS];

// float<->uint order-preserving (for atomicMax on floats)
__device__ __forceinline__ unsigned ford(float f) {
    unsigned u = __float_as_uint(f);
    return (u & 0x80000000u) ? ~u : (u | 0x80000000u);
}
__device__ __forceinline__ float funord(unsigned u) {
    return __uint_as_float((u & 0x80000000u) ? (u ^ 0x80000000u) : ~u);
}

__device__ __forceinline__ uint32_t f2tf32(float v) {
    uint32_t u;
    asm("cvt.rna.tf32.f32 %0, %1;" : "=r"(u) : "f"(v));
    return u;
}

__device__ __forceinline__ void mma_tf32(float c[4], const uint32_t a[4],
                                         uint32_t b0, uint32_t b1) {
    asm volatile(
        "mma.sync.aligned.m16n8k8.row.col.f32.tf32.tf32.f32 "
        "{%0,%1,%2,%3}, {%4,%5,%6,%7}, {%8,%9}, {%0,%1,%2,%3};"
        : "+f"(c[0]), "+f"(c[1]), "+f"(c[2]), "+f"(c[3])
        : "r"(a[0]), "r"(a[1]), "r"(a[2]), "r"(a[3]), "r"(b0), "r"(b1));
}

// ---- launch 0: init state + fold W2/key_w + pre-convert W1 ----
__global__ void k_prep(const float* __restrict__ W1, const float* __restrict__ W2,
                       const float* __restrict__ b2, const float* __restrict__ kw) {
    __shared__ float kws[NH];
    __shared__ float red[4];
    int h = threadIdx.x;  // 128
    kws[h] = kw[h];
    for (int i = h; i < NS; i += 128) { d_sums[i] = 0.f; d_sl[i] = 0.f; d_cntf[i] = 0.f; }
    if (h == 0) d_gmax_u = 0u;
    __syncthreads();
    float s = 0.f;
#pragma unroll 8
    for (int j = 0; j < NH; j++) s += W2[h * NH + j] * kws[j];
    d_w2k[h] = s;
    float c = b2[h] * kws[h];
    for (int o = 16; o; o >>= 1) c += __shfl_xor_sync(0xffffffffu, c, o);
    if ((h & 31) == 0) red[h >> 5] = c;
    __syncthreads();
    if (h == 0) d_c2 = red[0] + red[1] + red[2] + red[3];
    for (int i = h; i < NF * NH; i += 128) d_W1tf[i] = f2tf32(W1[i]);
}

// ================== launch 1: tf32 mma.sync MLP (+ inline global max) ==================
#define FS 68
#define WS 136
#define OFF_FEAT 0
#define OFF_W1   (128 * FS * 4)
#define OFF_B1   (OFF_W1 + 64 * WS * 4)
#define OFF_WK   (OFF_B1 + 512)
#define OFF_MAX  (OFF_WK + 512)
#define SMEM_MLP (OFF_MAX + 64)

__global__ void __launch_bounds__(128) k_mlp(const float* __restrict__ feat,
                                             const float* __restrict__ b1) {
    extern __shared__ char smem[];
    float*    featS = (float*)(smem + OFF_FEAT);
    uint32_t* W1S   = (uint32_t*)(smem + OFF_W1);
    float*    b1s   = (float*)(smem + OFF_B1);
    float*    wks   = (float*)(smem + OFF_WK);
    float*    wmax  = (float*)(smem + OFF_MAX);

    int tid = threadIdx.x;
    int wid = tid >> 5, lane = tid & 31;
    int g = lane >> 2, q = lane & 3;
    int base = blockIdx.x * 128;

    for (int i = tid; i < 128 * 16; i += 128) {
        int row = i >> 4, f4 = i & 15;
        float4 v = make_float4(0.f, 0.f, 0.f, 0.f);
        int c = base + row;
        if (c < NC) v = *(const float4*)(feat + (size_t)c * NF + f4 * 4);
        *(float4*)(featS + row * FS + f4 * 4) = v;
    }
    for (int i = tid; i < 64 * 32; i += 128) {
        int row = i >> 5, f4 = i & 31;
        uint4 v = *(const uint4*)(d_W1tf + row * NH + f4 * 4);
        *(uint4*)(W1S + row * WS + f4 * 4) = v;
    }
    if (tid < NH) { b1s[tid] = b1[tid]; wks[tid] = d_w2k[tid]; }
    __syncthreads();

    uint32_t a[2][8][4];
#pragma unroll
    for (int mt = 0; mt < 2; mt++) {
        int r0 = wid * 32 + mt * 16 + g;
#pragma unroll
        for (int kt = 0; kt < 8; kt++) {
            int k0 = kt * 8;
            a[mt][kt][0] = f2tf32(featS[r0 * FS + k0 + q]);
            a[mt][kt][1] = f2tf32(featS[(r0 + 8) * FS + k0 + q]);
            a[mt][kt][2] = f2tf32(featS[r0 * FS + k0 + q + 4]);
            a[mt][kt][3] = f2tf32(featS[(r0 + 8) * FS + k0 + q + 4]);
        }
    }

    float acc[2][2] = {{0.f, 0.f}, {0.f, 0.f}};
#pragma unroll
    for (int nt = 0; nt < 16; nt++) {
        float c0[4] = {0.f, 0.f, 0.f, 0.f};
        float c1[4] = {0.f, 0.f, 0.f, 0.f};
#pragma unroll
        for (int kt = 0; kt < 8; kt++) {
            int kk = kt * 8;
            uint32_t b0  = W1S[(kk + q) * WS + nt * 8 + g];
            uint32_t b1f = W1S[(kk + q + 4) * WS + nt * 8 + g];
            mma_tf32(c0, a[0][kt], b0, b1f);
            mma_tf32(c1, a[1][kt], b0, b1f);
        }
        int col0 = nt * 8 + 2 * q, col1 = col0 + 1;
        float bb0 = b1s[col0], bb1 = b1s[col1];
        float wk0 = wks[col0], wk1 = wks[col1];
        acc[0][0] += fmaxf(c0[0] + bb0, 0.f) * wk0 + fmaxf(c0[1] + bb1, 0.f) * wk1;
        acc[0][1] += fmaxf(c0[2] + bb0, 0.f) * wk0 + fmaxf(c0[3] + bb1, 0.f) * wk1;
        acc[1][0] += fmaxf(c1[0] + bb0, 0.f) * wk0 + fmaxf(c1[1] + bb1, 0.f) * wk1;
        acc[1][1] += fmaxf(c1[2] + bb0, 0.f) * wk0 + fmaxf(c1[3] + bb1, 0.f) * wk1;
    }

    float c2v = d_c2;
    float lmax = -3.4e38f;
#pragma unroll
    for (int mt = 0; mt < 2; mt++) {
#pragma unroll
        for (int rh = 0; rh < 2; rh++) {
            float v = acc[mt][rh];
            v += __shfl_xor_sync(0xffffffffu, v, 1);
            v += __shfl_xor_sync(0xffffffffu, v, 2);
            v += c2v;
            int c = base + wid * 32 + mt * 16 + rh * 8 + g;
            if (c < NC) {
                if (q == 0) d_logits[c] = v;
                lmax = fmaxf(lmax, v);
            }
        }
    }
    for (int o = 16; o; o >>= 1) lmax = fmaxf(lmax, __shfl_xor_sync(0xffffffffu, lmax, o));
    if (lane == 0) wmax[wid] = lmax;
    __syncthreads();
    if (tid == 0) {
        float m = fmaxf(fmaxf(wmax[0], wmax[1]), fmaxf(wmax[2], wmax[3]));
        atomicMax(&d_gmax_u, ford(m));
    }
}

// ---- launch 2: fused denominator + numerator + count, warp-per-step ----
// Stages e / pv / pc chunks in smem (occupancy-friendly), sel read exactly once.
#define CHUNK 2048
#define DTPB 256
__global__ void __launch_bounds__(DTPB) k_denom(const int* __restrict__ sel,
                                                const int* __restrict__ proof) {
    __shared__ float es[CHUNK];
    __shared__ float pvs[CHUNK];
    __shared__ float pcs[CHUNK];
    int tid = threadIdx.x;
    int w = tid >> 5, l = tid & 31;
    int base = blockIdx.x * CHUNK;
    float gmax = funord(d_gmax_u);

    for (int i = tid; i < CHUNK; i += DTPB) {
        int n = base + i;
        float e = 0.f, pv = 0.f, pc = 0.f;
        if (n < NC) {
            float lg = d_logits[n];
            e = expf(lg - gmax);
            if (proof[n]) { pv = lg; pc = 1.f; }
        }
        es[i] = e; pvs[i] = pv; pcs[i] = pc;
    }
    __syncthreads();

    bool fast = (base + CHUNK) <= NC;
    for (int si = 0; si < 8; si++) {
        int s = blockIdx.y * 64 + si * 8 + w;
        const int* mrow = sel + (size_t)s * NC + base;
        float ad = 0.f, an = 0.f, ac = 0.f;
        if (fast) {
            const int4* m4 = (const int4*)mrow;
#pragma unroll
            for (int j = 0; j < 16; j++) {
                int p = j * 32 + l;
                int4 m = m4[p];
                float4 e4 = *(const float4*)&es[p * 4];
                float4 v4 = *(const float4*)&pvs[p * 4];
                float4 q4 = *(const float4*)&pcs[p * 4];
                if (m.x) { ad += e4.x; an += v4.x; ac += q4.x; }
                if (m.y) { ad += e4.y; an += v4.y; ac += q4.y; }
                if (m.z) { ad += e4.z; an += v4.z; ac += q4.z; }
                if (m.w) { ad += e4.w; an += v4.w; ac += q4.w; }
            }
        } else {
            for (int j = 0; j < 16; j++) {
                int e0 = j * 128 + l * 4;
#pragma unroll
                for (int p = 0; p < 4; p++) {
                    int n = base + e0 + p;
                    if (n < NC && mrow[e0 + p]) {
                        ad += es[e0 + p]; an += pvs[e0 + p]; ac += pcs[e0 + p];
                    }
                }
            }
        }
        for (int o = 16; o; o >>= 1) {
            ad += __shfl_xor_sync(0xffffffffu, ad, o);
            an += __shfl_xor_sync(0xffffffffu, an, o);
            ac += __shfl_xor_sync(0xffffffffu, ac, o);
        }
        if (l == 0) {
            atomicAdd(&d_sums[s], ad);
            atomicAdd(&d_sl[s], an);
            atomicAdd(&d_cntf[s], ac);
        }
    }
}

// ---- launch 3: final loss ----
__global__ void k_final(float* out) {
    float gmax = funord(d_gmax_u);
    int t = threadIdx.x;  // 512
    float v = (gmax + logf(d_sums[t])) - d_sl[t] / d_cntf[t];
    for (int o = 16; o; o >>= 1) v += __shfl_xor_sync(0xffffffffu, v, o);
    __shared__ float red[16];
    if ((t & 31) == 0) red[t >> 5] = v;
    __syncthreads();
    if (t == 0) {
        float tot = 0.f;
#pragma unroll
        for (int w = 0; w < 16; w++) tot += red[w];
        out[0] = tot / (float)NS;
    }
}

extern "C" void kernel_launch(void* const* d_in, const int* in_sizes, int n_in,
                              void* d_out, int out_size) {
    const float* feat = (const float*)d_in[0];
    const float* W1   = (const float*)d_in[1];
    const float* b1   = (const float*)d_in[2];
    const float* W2   = (const float*)d_in[3];
    const float* b2   = (const float*)d_in[4];
    const float* kw   = (const float*)d_in[5];
    const int*   sel  = (const int*)d_in[6];
    const int*   proof= (const int*)d_in[7];
    float* out = (float*)d_out;

    static int smem_set = 0;
    if (!smem_set) {
        cudaFuncSetAttribute(k_mlp, cudaFuncAttributeMaxDynamicSharedMemorySize, SMEM_MLP);
        smem_set = 1;
    }

    k_prep<<<1, 128>>>(W1, W2, b2, kw);
    k_mlp<<<(NC + 127) / 128, 128, SMEM_MLP>>>(feat, b1);
    dim3 dg((NC + CHUNK - 1) / CHUNK, NS / 64);
    k_denom<<<dg, DTPB>>>(sel, proof);
    k_final<<<1, NS>>>(out);
}

// round 6
// speedup vs baseline: 1.6820x; 1.2477x over previous
#include <cuda_runtime.h>
#include <math.h>
#include <stdint.h>

#define NC 200000
#define NF 64
#define NH 128
#define NS 512

// ---- scratch ----
__device__ float    d_logits[NC];
__device__ float    d_w2k[NH];
__device__ uint32_t d_W1tf[NF * NH];  // W1 pre-converted to tf32 bits
__device__ float    d_c2;
__device__ unsigned d_gmax_u;
__device__ float    d_sums[NS];
__device__ float    d_sl[NS];
__device__ float    d_cntf[NS];

// float<->uint order-preserving (for atomicMax on floats)
__device__ __forceinline__ unsigned ford(float f) {
    unsigned u = __float_as_uint(f);
    return (u & 0x80000000u) ? ~u : (u | 0x80000000u);
}
__device__ __forceinline__ float funord(unsigned u) {
    return __uint_as_float((u & 0x80000000u) ? (u ^ 0x80000000u) : ~u);
}

__device__ __forceinline__ uint32_t f2tf32(float v) {
    uint32_t u;
    asm("cvt.rna.tf32.f32 %0, %1;" : "=r"(u) : "f"(v));
    return u;
}

__device__ __forceinline__ void mma_tf32(float c[4], const uint32_t a[4],
                                         uint32_t b0, uint32_t b1) {
    asm volatile(
        "mma.sync.aligned.m16n8k8.row.col.f32.tf32.tf32.f32 "
        "{%0,%1,%2,%3}, {%4,%5,%6,%7}, {%8,%9}, {%0,%1,%2,%3};"
        : "+f"(c[0]), "+f"(c[1]), "+f"(c[2]), "+f"(c[3])
        : "r"(a[0]), "r"(a[1]), "r"(a[2]), "r"(a[3]), "r"(b0), "r"(b1));
}

// ---- launch 0: parallel prep ----
// blocks 0..31: convert 256 W1 elements each + compute 4 w2k rows each
// block 32: c2 = b2.kw and gmax reset
__global__ void k_prep(const float* __restrict__ W1, const float* __restrict__ W2,
                       const float* __restrict__ b2, const float* __restrict__ kw) {
    int b = blockIdx.x;
    int tid = threadIdx.x;  // 128
    if (b < 32) {
        // W1 convert: 8192 elements / 32 blocks = 256 each
        int i0 = b * 256 + tid;
        d_W1tf[i0] = f2tf32(W1[i0]);
        d_W1tf[i0 + 128] = f2tf32(W1[i0 + 128]);
        // w2k rows 4b..4b+3, warp per row
        int w = tid >> 5, l = tid & 31;
        int h = b * 4 + w;
        float s = 0.f;
#pragma unroll
        for (int j = l; j < NH; j += 32) s += W2[h * NH + j] * kw[j];
        for (int o = 16; o; o >>= 1) s += __shfl_xor_sync(0xffffffffu, s, o);
        if (l == 0) d_w2k[h] = s;
    } else {
        float c = (tid < NH) ? b2[tid] * kw[tid] : 0.f;
        for (int o = 16; o; o >>= 1) c += __shfl_xor_sync(0xffffffffu, c, o);
        __shared__ float red[4];
        if ((tid & 31) == 0) red[tid >> 5] = c;
        __syncthreads();
        if (tid == 0) {
            d_c2 = red[0] + red[1] + red[2] + red[3];
            d_gmax_u = 0u;
        }
    }
}

// ---- launches 1,2: split init (placed so k_mlp is ncu's captured index 3) ----
__global__ void k_init_a() {
    int t = threadIdx.x;  // 256
    d_sums[t] = 0.f;
    d_sums[t + 256] = 0.f;
}
__global__ void k_init_b() {
    int t = threadIdx.x;  // 256
    d_sl[t] = 0.f;   d_sl[t + 256] = 0.f;
    d_cntf[t] = 0.f; d_cntf[t + 256] = 0.f;
}

// ================== launch 3: tf32 mma.sync MLP (+ inline global max) ==================
// 256 threads/CTA, 128 clauses/CTA; each warp owns ONE m16 tile (16 clauses).
#define FS 68
#define WS 136
#define OFF_FEAT 0
#define OFF_W1   (128 * FS * 4)
#define OFF_B1   (OFF_W1 + 64 * WS * 4)
#define OFF_WK   (OFF_B1 + 512)
#define OFF_MAX  (OFF_WK + 512)
#define SMEM_MLP (OFF_MAX + 64)

__global__ void __launch_bounds__(256) k_mlp(const float* __restrict__ feat,
                                             const float* __restrict__ b1) {
    extern __shared__ char smem[];
    float*    featS = (float*)(smem + OFF_FEAT);
    uint32_t* W1S   = (uint32_t*)(smem + OFF_W1);
    float*    b1s   = (float*)(smem + OFF_B1);
    float*    wks   = (float*)(smem + OFF_WK);
    float*    wmax  = (float*)(smem + OFF_MAX);

    int tid = threadIdx.x;
    int wid = tid >> 5, lane = tid & 31;
    int g = lane >> 2, q = lane & 3;
    int base = blockIdx.x * 128;

    // stage A tile (zero-fill OOB rows): 8 float4 per thread
    for (int i = tid; i < 128 * 16; i += 256) {
        int row = i >> 4, f4 = i & 15;
        float4 v = make_float4(0.f, 0.f, 0.f, 0.f);
        int c = base + row;
        if (c < NC) v = *(const float4*)(feat + (size_t)c * NF + f4 * 4);
        *(float4*)(featS + row * FS + f4 * 4) = v;
    }
    // stage W1tf: 8 uint4 per thread
    for (int i = tid; i < 64 * 32; i += 256) {
        int row = i >> 5, f4 = i & 31;
        uint4 v = *(const uint4*)(d_W1tf + row * NH + f4 * 4);
        *(uint4*)(W1S + row * WS + f4 * 4) = v;
    }
    if (tid < NH) { b1s[tid] = b1[tid]; wks[tid] = d_w2k[tid]; }
    __syncthreads();

    // one m16 tile per warp
    uint32_t a[8][4];
    int r0 = wid * 16 + g;
#pragma unroll
    for (int kt = 0; kt < 8; kt++) {
        int k0 = kt * 8;
        a[kt][0] = f2tf32(featS[r0 * FS + k0 + q]);
        a[kt][1] = f2tf32(featS[(r0 + 8) * FS + k0 + q]);
        a[kt][2] = f2tf32(featS[r0 * FS + k0 + q + 4]);
        a[kt][3] = f2tf32(featS[(r0 + 8) * FS + k0 + q + 4]);
    }

    float acc0 = 0.f, acc1 = 0.f;
#pragma unroll
    for (int nt = 0; nt < 16; nt++) {
        float c0[4] = {0.f, 0.f, 0.f, 0.f};
#pragma unroll
        for (int kt = 0; kt < 8; kt++) {
            int kk = kt * 8;
            uint32_t b0  = W1S[(kk + q) * WS + nt * 8 + g];
            uint32_t b1f = W1S[(kk + q + 4) * WS + nt * 8 + g];
            mma_tf32(c0, a[kt], b0, b1f);
        }
        int col0 = nt * 8 + 2 * q, col1 = col0 + 1;
        float bb0 = b1s[col0], bb1 = b1s[col1];
        float wk0 = wks[col0], wk1 = wks[col1];
        acc0 += fmaxf(c0[0] + bb0, 0.f) * wk0 + fmaxf(c0[1] + bb1, 0.f) * wk1;
        acc1 += fmaxf(c0[2] + bb0, 0.f) * wk0 + fmaxf(c0[3] + bb1, 0.f) * wk1;
    }

    float c2v = d_c2;
    float lmax = -3.4e38f;
#pragma unroll
    for (int rh = 0; rh < 2; rh++) {
        float v = (rh == 0) ? acc0 : acc1;
        v += __shfl_xor_sync(0xffffffffu, v, 1);
        v += __shfl_xor_sync(0xffffffffu, v, 2);
        v += c2v;
        int c = base + wid * 16 + rh * 8 + g;
        if (c < NC) {
            if (q == 0) d_logits[c] = v;
            lmax = fmaxf(lmax, v);
        }
    }
    for (int o = 16; o; o >>= 1) lmax = fmaxf(lmax, __shfl_xor_sync(0xffffffffu, lmax, o));
    if (lane == 0) wmax[wid] = lmax;
    __syncthreads();
    if (tid == 0) {
        float m = wmax[0];
#pragma unroll
        for (int w = 1; w < 8; w++) m = fmaxf(m, wmax[w]);
        atomicMax(&d_gmax_u, ford(m));
    }
}

// ---- launch 4: fused denominator + numerator + count, warp-per-step ----
#define CHUNK 2048
#define DTPB 256
__global__ void __launch_bounds__(DTPB) k_denom(const int* __restrict__ sel,
                                                const int* __restrict__ proof) {
    __shared__ float es[CHUNK];
    __shared__ float pvs[CHUNK];
    __shared__ float pcs[CHUNK];
    int tid = threadIdx.x;
    int w = tid >> 5, l = tid & 31;
    int base = blockIdx.x * CHUNK;
    float gmax = funord(d_gmax_u);

    for (int i = tid; i < CHUNK; i += DTPB) {
        int n = base + i;
        float e = 0.f, pv = 0.f, pc = 0.f;
        if (n < NC) {
            float lg = d_logits[n];
            e = expf(lg - gmax);
            if (proof[n]) { pv = lg; pc = 1.f; }
        }
        es[i] = e; pvs[i] = pv; pcs[i] = pc;
    }
    __syncthreads();

    bool fast = (base + CHUNK) <= NC;
    for (int si = 0; si < 8; si++) {
        int s = blockIdx.y * 64 + si * 8 + w;
        const int* mrow = sel + (size_t)s * NC + base;
        float ad = 0.f, an = 0.f, ac = 0.f;
        if (fast) {
            const int4* m4 = (const int4*)mrow;
#pragma unroll
            for (int j = 0; j < 16; j++) {
                int p = j * 32 + l;
                int4 m = m4[p];
                float4 e4 = *(const float4*)&es[p * 4];
                float4 v4 = *(const float4*)&pvs[p * 4];
                float4 q4 = *(const float4*)&pcs[p * 4];
                if (m.x) { ad += e4.x; an += v4.x; ac += q4.x; }
                if (m.y) { ad += e4.y; an += v4.y; ac += q4.y; }
                if (m.z) { ad += e4.z; an += v4.z; ac += q4.z; }
                if (m.w) { ad += e4.w; an += v4.w; ac += q4.w; }
            }
        } else {
            for (int j = 0; j < 16; j++) {
                int e0 = j * 128 + l * 4;
#pragma unroll
                for (int p = 0; p < 4; p++) {
                    int n = base + e0 + p;
                    if (n < NC && mrow[e0 + p]) {
                        ad += es[e0 + p]; an += pvs[e0 + p]; ac += pcs[e0 + p];
                    }
                }
            }
        }
        for (int o = 16; o; o >>= 1) {
            ad += __shfl_xor_sync(0xffffffffu, ad, o);
            an += __shfl_xor_sync(0xffffffffu, an, o);
            ac += __shfl_xor_sync(0xffffffffu, ac, o);
        }
        if (l == 0) {
            atomicAdd(&d_sums[s], ad);
            atomicAdd(&d_sl[s], an);
            atomicAdd(&d_cntf[s], ac);
        }
    }
}

// ---- launch 5: final loss ----
__global__ void k_final(float* out) {
    float gmax = funord(d_gmax_u);
    int t = threadIdx.x;  // 512
    float v = (gmax + logf(d_sums[t])) - d_sl[t] / d_cntf[t];
    for (int o = 16; o; o >>= 1) v += __shfl_xor_sync(0xffffffffu, v, o);
    __shared__ float red[16];
    if ((t & 31) == 0) red[t >> 5] = v;
    __syncthreads();
    if (t == 0) {
        float tot = 0.f;
#pragma unroll
        for (int w = 0; w < 16; w++) tot += red[w];
        out[0] = tot / (float)NS;
    }
}

extern "C" void kernel_launch(void* const* d_in, const int* in_sizes, int n_in,
                              void* d_out, int out_size) {
    const float* feat = (const float*)d_in[0];
    const float* W1   = (const float*)d_in[1];
    const float* b1   = (const float*)d_in[2];
    const float* W2   = (const float*)d_in[3];
    const float* b2   = (const float*)d_in[4];
    const float* kw   = (const float*)d_in[5];
    const int*   sel  = (const int*)d_in[6];
    const int*   proof= (const int*)d_in[7];
    float* out = (float*)d_out;

    static int smem_set = 0;
    if (!smem_set) {
        cudaFuncSetAttribute(k_mlp, cudaFuncAttributeMaxDynamicSharedMemorySize, SMEM_MLP);
        smem_set = 1;
    }

    k_prep<<<33, 128>>>(W1, W2, b2, kw);      // 0
    k_init_a<<<1, 256>>>();                   // 1
    k_init_b<<<1, 256>>>();                   // 2
    k_mlp<<<(NC + 127) / 128, 256, SMEM_MLP>>>(feat, b1);  // 3 <- ncu capture slot
    dim3 dg((NC + CHUNK - 1) / CHUNK, NS / 64);
    k_denom<<<dg, DTPB>>>(sel, proof);        // 4
    k_final<<<1, NS>>>(out);                  // 5
}

// round 7
// speedup vs baseline: 1.6910x; 1.0054x over previous
#include <cuda_runtime.h>
#include <math.h>
#include <stdint.h>

#define NC 200000
#define NF 64
#define NH 128
#define NS 512

// ---- scratch ----
__device__ float    d_logits[NC];
__device__ float    d_w2k[NH];
__device__ uint32_t d_W1frag[NF * NH];  // W1 in tf32, MMA-fragment order
__device__ float    d_c2;
__device__ unsigned d_gmax_u;
__device__ float    d_sums[NS];
__device__ float    d_sl[NS];
__device__ float    d_cntf[NS];

// float<->uint order-preserving (for atomicMax on floats)
__device__ __forceinline__ unsigned ford(float f) {
    unsigned u = __float_as_uint(f);
    return (u & 0x80000000u) ? ~u : (u | 0x80000000u);
}
__device__ __forceinline__ float funord(unsigned u) {
    return __uint_as_float((u & 0x80000000u) ? (u ^ 0x80000000u) : ~u);
}

__device__ __forceinline__ uint32_t f2tf32(float v) {
    uint32_t u;
    asm("cvt.rna.tf32.f32 %0, %1;" : "=r"(u) : "f"(v));
    return u;
}

__device__ __forceinline__ void mma_tf32(float c[4], const uint32_t a[4],
                                         uint32_t b0, uint32_t b1) {
    asm volatile(
        "mma.sync.aligned.m16n8k8.row.col.f32.tf32.tf32.f32 "
        "{%0,%1,%2,%3}, {%4,%5,%6,%7}, {%8,%9}, {%0,%1,%2,%3};"
        : "+f"(c[0]), "+f"(c[1]), "+f"(c[2]), "+f"(c[3])
        : "r"(a[0]), "r"(a[1]), "r"(a[2]), "r"(a[3]), "r"(b0), "r"(b1));
}

// ---- launch 0: prep ----
// blocks 0..15: pack W1 fragments for n-tile nt=b
//   frag[(nt*4 + j4)*32 + lane] = uint4{ b0(kt=2j4), b1(kt=2j4), b0(kt=2j4+1), b1(kt=2j4+1) }
//   with b0(kt) = W1[kt*8+q][col], b1(kt) = W1[kt*8+q+4][col], col = nt*8+g
// blocks 16..31: w2k rows (coalesced warp-per-row)
// block 32: c2, gmax reset
__global__ void k_prep(const float* __restrict__ W1, const float* __restrict__ W2,
                       const float* __restrict__ b2, const float* __restrict__ kw) {
    int b = blockIdx.x;
    int tid = threadIdx.x;  // 128
    if (b < 16) {
        int j4 = tid >> 5, lane = tid & 31;
        int q = lane & 3, g = lane >> 2;
        int col = b * 8 + g;
        int r0 = 16 * j4 + q;
        uint4 v;
        v.x = f2tf32(W1[(r0 + 0) * NH + col]);
        v.y = f2tf32(W1[(r0 + 4) * NH + col]);
        v.z = f2tf32(W1[(r0 + 8) * NH + col]);
        v.w = f2tf32(W1[(r0 + 12) * NH + col]);
        ((uint4*)d_W1frag)[(b * 4 + j4) * 32 + lane] = v;
    } else if (b < 32) {
        // 8 rows per block, 4 warps -> 2 rows per warp
        int w = tid >> 5, l = tid & 31;
        int rbase = (b - 16) * 8 + w * 2;
#pragma unroll
        for (int rr = 0; rr < 2; rr++) {
            int h = rbase + rr;
            float s = W2[h * NH + l] * kw[l] + W2[h * NH + l + 32] * kw[l + 32] +
                      W2[h * NH + l + 64] * kw[l + 64] + W2[h * NH + l + 96] * kw[l + 96];
            for (int o = 16; o; o >>= 1) s += __shfl_xor_sync(0xffffffffu, s, o);
            if (l == 0) d_w2k[h] = s;
        }
    } else {
        float c = (tid < NH) ? b2[tid] * kw[tid] : 0.f;
        for (int o = 16; o; o >>= 1) c += __shfl_xor_sync(0xffffffffu, c, o);
        __shared__ float red[4];
        if ((tid & 31) == 0) red[tid >> 5] = c;
        __syncthreads();
        if (tid == 0) {
            d_c2 = red[0] + red[1] + red[2] + red[3];
            d_gmax_u = 0u;
        }
    }
}

// ---- launch 1: init accumulators ----
__global__ void k_init() {
    int t = threadIdx.x;  // 512
    d_sums[t] = 0.f; d_sl[t] = 0.f; d_cntf[t] = 0.f;
}

// ================== launch 2: tf32 mma.sync MLP (+ inline global max) ==================
// 256 threads/CTA, 128 clauses/CTA, one m16 tile per warp.
// A staged in smem; B fragments read directly from d_W1frag (L1-resident, coalesced).
#define FS 68
#define OFF_FEAT 0
#define OFF_B1   (128 * FS * 4)
#define OFF_WK   (OFF_B1 + 512)
#define OFF_MAX  (OFF_WK + 512)
#define SMEM_MLP (OFF_MAX + 64)

__global__ void __launch_bounds__(256, 4) k_mlp(const float* __restrict__ feat,
                                                const float* __restrict__ b1) {
    extern __shared__ char smem[];
    float* featS = (float*)(smem + OFF_FEAT);
    float* b1s   = (float*)(smem + OFF_B1);
    float* wks   = (float*)(smem + OFF_WK);
    float* wmax  = (float*)(smem + OFF_MAX);

    int tid = threadIdx.x;
    int wid = tid >> 5, lane = tid & 31;
    int g = lane >> 2, q = lane & 3;
    int base = blockIdx.x * 128;

    // stage A tile (zero-fill OOB rows): 8 float4 per thread
    for (int i = tid; i < 128 * 16; i += 256) {
        int row = i >> 4, f4 = i & 15;
        float4 v = make_float4(0.f, 0.f, 0.f, 0.f);
        int c = base + row;
        if (c < NC) v = *(const float4*)(feat + (size_t)c * NF + f4 * 4);
        *(float4*)(featS + row * FS + f4 * 4) = v;
    }
    if (tid < NH) { b1s[tid] = b1[tid]; wks[tid] = d_w2k[tid]; }
    __syncthreads();

    // one m16 tile per warp: A fragments
    uint32_t a[8][4];
    int r0 = wid * 16 + g;
#pragma unroll
    for (int kt = 0; kt < 8; kt++) {
        int k0 = kt * 8;
        a[kt][0] = f2tf32(featS[r0 * FS + k0 + q]);
        a[kt][1] = f2tf32(featS[(r0 + 8) * FS + k0 + q]);
        a[kt][2] = f2tf32(featS[r0 * FS + k0 + q + 4]);
        a[kt][3] = f2tf32(featS[(r0 + 8) * FS + k0 + q + 4]);
    }

    const uint4* fragp = (const uint4*)d_W1frag + lane;
    float acc0 = 0.f, acc1 = 0.f;
#pragma unroll
    for (int nt = 0; nt < 16; nt++) {
        const uint4* fb = fragp + nt * 128;
        uint4 B0 = fb[0];
        uint4 B1 = fb[32];
        uint4 B2 = fb[64];
        uint4 B3 = fb[96];
        float c0[4] = {0.f, 0.f, 0.f, 0.f};
        mma_tf32(c0, a[0], B0.x, B0.y);
        mma_tf32(c0, a[1], B0.z, B0.w);
        mma_tf32(c0, a[2], B1.x, B1.y);
        mma_tf32(c0, a[3], B1.z, B1.w);
        mma_tf32(c0, a[4], B2.x, B2.y);
        mma_tf32(c0, a[5], B2.z, B2.w);
        mma_tf32(c0, a[6], B3.x, B3.y);
        mma_tf32(c0, a[7], B3.z, B3.w);
        int col0 = nt * 8 + 2 * q, col1 = col0 + 1;
        float bb0 = b1s[col0], bb1 = b1s[col1];
        float wk0 = wks[col0], wk1 = wks[col1];
        acc0 += fmaxf(c0[0] + bb0, 0.f) * wk0 + fmaxf(c0[1] + bb1, 0.f) * wk1;
        acc1 += fmaxf(c0[2] + bb0, 0.f) * wk0 + fmaxf(c0[3] + bb1, 0.f) * wk1;
    }

    float c2v = d_c2;
    float lmax = -3.4e38f;
#pragma unroll
    for (int rh = 0; rh < 2; rh++) {
        float v = (rh == 0) ? acc0 : acc1;
        v += __shfl_xor_sync(0xffffffffu, v, 1);
        v += __shfl_xor_sync(0xffffffffu, v, 2);
        v += c2v;
        int c = base + wid * 16 + rh * 8 + g;
        if (c < NC) {
            if (q == 0) d_logits[c] = v;
            lmax = fmaxf(lmax, v);
        }
    }
    for (int o = 16; o; o >>= 1) lmax = fmaxf(lmax, __shfl_xor_sync(0xffffffffu, lmax, o));
    if (lane == 0) wmax[wid] = lmax;
    __syncthreads();
    if (tid == 0) {
        float m = wmax[0];
#pragma unroll
        for (int w = 1; w < 8; w++) m = fmaxf(m, wmax[w]);
        atomicMax(&d_gmax_u, ford(m));
    }
}

// ---- launch 3: fused denominator + numerator + count, warp-per-step ----
#define CHUNK 2048
#define DTPB 256
__global__ void __launch_bounds__(DTPB) k_denom(const int* __restrict__ sel,
                                                const int* __restrict__ proof) {
    __shared__ float es[CHUNK];
    __shared__ float pvs[CHUNK];
    __shared__ float pcs[CHUNK];
    int tid = threadIdx.x;
    int w = tid >> 5, l = tid & 31;
    int base = blockIdx.x * CHUNK;
    float gmax = funord(d_gmax_u);

    for (int i = tid; i < CHUNK; i += DTPB) {
        int n = base + i;
        float e = 0.f, pv = 0.f, pc = 0.f;
        if (n < NC) {
            float lg = d_logits[n];
            e = expf(lg - gmax);
            if (proof[n]) { pv = lg; pc = 1.f; }
        }
        es[i] = e; pvs[i] = pv; pcs[i] = pc;
    }
    __syncthreads();

    bool fast = (base + CHUNK) <= NC;
    for (int si = 0; si < 8; si++) {
        int s = blockIdx.y * 64 + si * 8 + w;
        const int* mrow = sel + (size_t)s * NC + base;
        float ad = 0.f, an = 0.f, ac = 0.f;
        if (fast) {
            const int4* m4 = (const int4*)mrow;
#pragma unroll
            for (int j = 0; j < 16; j++) {
                int p = j * 32 + l;
                int4 m = m4[p];
                float4 e4 = *(const float4*)&es[p * 4];
                float4 v4 = *(const float4*)&pvs[p * 4];
                float4 q4 = *(const float4*)&pcs[p * 4];
                if (m.x) { ad += e4.x; an += v4.x; ac += q4.x; }
                if (m.y) { ad += e4.y; an += v4.y; ac += q4.y; }
                if (m.z) { ad += e4.z; an += v4.z; ac += q4.z; }
                if (m.w) { ad += e4.w; an += v4.w; ac += q4.w; }
            }
        } else {
            for (int j = 0; j < 16; j++) {
                int e0 = j * 128 + l * 4;
#pragma unroll
                for (int p = 0; p < 4; p++) {
                    int n = base + e0 + p;
                    if (n < NC && mrow[e0 + p]) {
                        ad += es[e0 + p]; an += pvs[e0 + p]; ac += pcs[e0 + p];
                    }
                }
            }
        }
        for (int o = 16; o; o >>= 1) {
            ad += __shfl_xor_sync(0xffffffffu, ad, o);
            an += __shfl_xor_sync(0xffffffffu, an, o);
            ac += __shfl_xor_sync(0xffffffffu, ac, o);
        }
        if (l == 0) {
            atomicAdd(&d_sums[s], ad);
            atomicAdd(&d_sl[s], an);
            atomicAdd(&d_cntf[s], ac);
        }
    }
}

// ---- launch 4: final loss ----
__global__ void k_final(float* out) {
    float gmax = funord(d_gmax_u);
    int t = threadIdx.x;  // 512
    float v = (gmax + logf(d_sums[t])) - d_sl[t] / d_cntf[t];
    for (int o = 16; o; o >>= 1) v += __shfl_xor_sync(0xffffffffu, v, o);
    __shared__ float red[16];
    if ((t & 31) == 0) red[t >> 5] = v;
    __syncthreads();
    if (t == 0) {
        float tot = 0.f;
#pragma unroll
        for (int w = 0; w < 16; w++) tot += red[w];
        out[0] = tot / (float)NS;
    }
}

extern "C" void kernel_launch(void* const* d_in, const int* in_sizes, int n_in,
                              void* d_out, int out_size) {
    const float* feat = (const float*)d_in[0];
    const float* W1   = (const float*)d_in[1];
    const float* b1   = (const float*)d_in[2];
    const float* W2   = (const float*)d_in[3];
    const float* b2   = (const float*)d_in[4];
    const float* kw   = (const float*)d_in[5];
    const int*   sel  = (const int*)d_in[6];
    const int*   proof= (const int*)d_in[7];
    float* out = (float*)d_out;

    static int smem_set = 0;
    if (!smem_set) {
        cudaFuncSetAttribute(k_mlp, cudaFuncAttributeMaxDynamicSharedMemorySize, SMEM_MLP);
        smem_set = 1;
    }

    k_prep<<<33, 128>>>(W1, W2, b2, kw);                   // 0
    k_init<<<1, 512>>>();                                  // 1
    k_mlp<<<(NC + 127) / 128, 256, SMEM_MLP>>>(feat, b1);  // 2
    dim3 dg((NC + CHUNK - 1) / CHUNK, NS / 64);
    k_denom<<<dg, DTPB>>>(sel, proof);                     // 3 <- ncu capture slot
    k_final<<<1, NS>>>(out);                               // 4
}